// round 1
// baseline (speedup 1.0000x reference)
#include <cuda_runtime.h>
#include <math.h>

// Problem constants
#define Bq   2
#define Tt   1024
#define Cc   1024
#define Hh   16
#define Ll   6
#define HSs  64
#define Vv   32000
#define FF   4096
#define MR   (Bq*Tt)          // 2048 rows

// Scratch (device globals: allocation-free)
__device__ __align__(128) float g_x   [MR * Cc];        // residual stream
__device__ __align__(128) float g_h   [MR * Cc];        // ln output / attn output
__device__ __align__(128) float g_qkv [MR * 3 * Cc];    // q|k|v, col = which*1024 + h*64 + d
__device__ __align__(128) float g_mlp [MR * FF];        // mlp hidden
__device__ __align__(128) float g_wqkv[Ll * Cc * 3 * Cc]; // repacked qkv weights

// ---------------------------------------------------------------------------
// Repack Wq/Wk/Wv (L,H,C,HS) -> g_wqkv (L,C,3C) with col = w*1024 + h*64 + d
// ---------------------------------------------------------------------------
__global__ void __launch_bounds__(256) repack_k(const float* __restrict__ Wq,
                                                const float* __restrict__ Wk,
                                                const float* __restrict__ Wv)
{
    const size_t total = (size_t)Ll * Cc * 3 * Cc;
    for (size_t i = (size_t)blockIdx.x * 256 + threadIdx.x; i < total;
         i += (size_t)gridDim.x * 256) {
        const size_t per_l = (size_t)Cc * 3 * Cc;
        int l = (int)(i / per_l);
        size_t r = i % per_l;
        int c = (int)(r / (3 * Cc));
        int n = (int)(r % (3 * Cc));
        int w = n >> 10;            // 0=q,1=k,2=v
        int cn = n & 1023;
        int hh = cn >> 6;
        int d  = cn & 63;
        const float* src = (w == 0) ? Wq : (w == 1) ? Wk : Wv;
        g_wqkv[i] = src[(((size_t)l * Hh + hh) * Cc + c) * HSs + d];
    }
}

// ---------------------------------------------------------------------------
// Embedding: x = tok_emb[idx] + pos_emb
// ---------------------------------------------------------------------------
__global__ void __launch_bounds__(256) embed_k(const int* __restrict__ idx,
                                               const float* __restrict__ tok,
                                               const float* __restrict__ pos)
{
    int i = blockIdx.x * 256 + threadIdx.x;        // over MR*Cc = 2,097,152
    int bt = i >> 10;
    int c  = i & 1023;
    int token = idx[bt];
    g_x[i] = tok[(size_t)token * Cc + c] + pos[i & (Tt * Cc - 1)];
}

// ---------------------------------------------------------------------------
// LayerNorm: one block per row (C=1024, 256 threads x float4)
// ---------------------------------------------------------------------------
__global__ void __launch_bounds__(256) ln_k(const float* __restrict__ x,
                                            const float* __restrict__ sc,
                                            const float* __restrict__ bi,
                                            float* __restrict__ y)
{
    const int row = blockIdx.x;
    const int tid = threadIdx.x;
    const float4 xv = ((const float4*)(x + (size_t)row * Cc))[tid];
    float s  = xv.x + xv.y + xv.z + xv.w;
    float s2 = xv.x*xv.x + xv.y*xv.y + xv.z*xv.z + xv.w*xv.w;
    __shared__ float r1[8], r2[8];
    #pragma unroll
    for (int o = 16; o; o >>= 1) {
        s  += __shfl_xor_sync(0xffffffffu, s,  o);
        s2 += __shfl_xor_sync(0xffffffffu, s2, o);
    }
    const int lane = tid & 31, w = tid >> 5;
    if (lane == 0) { r1[w] = s; r2[w] = s2; }
    __syncthreads();
    if (tid == 0) {
        float a = 0.f, b = 0.f;
        #pragma unroll
        for (int i = 0; i < 8; i++) { a += r1[i]; b += r2[i]; }
        r1[0] = a; r2[0] = b;
    }
    __syncthreads();
    const float mu   = r1[0] * (1.0f / Cc);
    const float var  = r2[0] * (1.0f / Cc) - mu * mu;
    const float rstd = rsqrtf(var + 1e-5f);
    const float4 sv = ((const float4*)sc)[tid];
    const float4 bv = ((const float4*)bi)[tid];
    float4 o;
    o.x = (xv.x - mu) * rstd * sv.x + bv.x;
    o.y = (xv.y - mu) * rstd * sv.y + bv.y;
    o.z = (xv.z - mu) * rstd * sv.z + bv.z;
    o.w = (xv.w - mu) * rstd * sv.w + bv.w;
    ((float4*)(y + (size_t)row * Cc))[tid] = o;
}

// ---------------------------------------------------------------------------
// GEMM: C(M,N) = A(M,K) @ B(K,N) [+bias] [+res] [relu]
// 128x128 block tile, 8x8 per-thread microtile, BK=8, 256 threads.
// Requires M%128==0, N%128==0, K%8==0 (true for all shapes here).
// ---------------------------------------------------------------------------
template<bool BIAS, bool RELU, bool RES>
__global__ void __launch_bounds__(256) gemm_k(
    const float* __restrict__ A, const float* __restrict__ B,
    const float* __restrict__ bias, const float* __restrict__ res,
    float* __restrict__ C, int M, int N, int K)
{
    __shared__ float As[8][132];
    __shared__ float Bs[8][132];
    const int tid = threadIdx.x;
    const int tx = tid & 15, ty = tid >> 4;
    const int bm = blockIdx.y << 7, bn = blockIdx.x << 7;

    const int arow = tid >> 1;            // 0..127
    const int acol = (tid & 1) << 2;      // 0 or 4
    const int brow = tid >> 5;            // 0..7
    const int bcol = (tid & 31) << 2;     // 0..124

    const float* Aptr = A + (size_t)(bm + arow) * K + acol;
    const float* Bptr = B + (size_t)brow * N + bn + bcol;

    float acc[8][8];
    #pragma unroll
    for (int i = 0; i < 8; i++)
        #pragma unroll
        for (int j = 0; j < 8; j++) acc[i][j] = 0.f;

    for (int kt = 0; kt < K; kt += 8) {
        float4 a4 = *(const float4*)(Aptr + kt);
        As[acol + 0][arow] = a4.x;
        As[acol + 1][arow] = a4.y;
        As[acol + 2][arow] = a4.z;
        As[acol + 3][arow] = a4.w;
        *(float4*)&Bs[brow][bcol] = *(const float4*)(Bptr + (size_t)kt * N);
        __syncthreads();
        #pragma unroll
        for (int k = 0; k < 8; ++k) {
            float ar[8], br[8];
            *(float4*)(ar)     = *(const float4*)&As[k][ty * 8];
            *(float4*)(ar + 4) = *(const float4*)&As[k][ty * 8 + 4];
            *(float4*)(br)     = *(const float4*)&Bs[k][tx * 8];
            *(float4*)(br + 4) = *(const float4*)&Bs[k][tx * 8 + 4];
            #pragma unroll
            for (int i = 0; i < 8; ++i)
                #pragma unroll
                for (int j = 0; j < 8; ++j)
                    acc[i][j] += ar[i] * br[j];
        }
        __syncthreads();
    }

    float bvals[8];
    if (BIAS) {
        *(float4*)(bvals)     = *(const float4*)&bias[bn + tx * 8];
        *(float4*)(bvals + 4) = *(const float4*)&bias[bn + tx * 8 + 4];
    }
    #pragma unroll
    for (int i = 0; i < 8; ++i) {
        const int row = bm + ty * 8 + i;
        float* crow = C + (size_t)row * N + bn + tx * 8;
        float v[8];
        #pragma unroll
        for (int j = 0; j < 8; ++j) {
            float t = acc[i][j];
            if (BIAS) t += bvals[j];
            v[j] = t;
        }
        if (RES) {
            const float* rrow = res + (size_t)row * N + bn + tx * 8;
            float4 r0 = *(const float4*)rrow;
            float4 r1 = *(const float4*)(rrow + 4);
            v[0] += r0.x; v[1] += r0.y; v[2] += r0.z; v[3] += r0.w;
            v[4] += r1.x; v[5] += r1.y; v[6] += r1.z; v[7] += r1.w;
        }
        if (RELU) {
            #pragma unroll
            for (int j = 0; j < 8; ++j) v[j] = fmaxf(v[j], 0.f);
        }
        *(float4*)crow       = make_float4(v[0], v[1], v[2], v[3]);
        *(float4*)(crow + 4) = make_float4(v[4], v[5], v[6], v[7]);
    }
}

// ---------------------------------------------------------------------------
// Attention: one block per (b, h, t) query row. Causal flash-free softmax.
// qkv row layout: [q(1024) | k(1024) | v(1024)], col within = h*64 + d.
// ---------------------------------------------------------------------------
__global__ void __launch_bounds__(256) attn_k(const float* __restrict__ qkv,
                                              float* __restrict__ out)
{
    const int t  = blockIdx.x;
    const int bh = blockIdx.y;
    const int b  = bh >> 4;
    const int hh = bh & 15;
    const int tid = threadIdx.x;
    const int lane = tid & 31, warp = tid >> 5;
    const int row = b * Tt + t;
    const int n = t + 1;

    __shared__ float qs[64];
    __shared__ float scs[Tt];
    __shared__ float rmax[8], rsum[8];
    __shared__ float osum[4][64];

    if (tid < 64) qs[tid] = qkv[(size_t)row * 3072 + hh * 64 + tid];
    __syncthreads();

    // scores: one warp per key position
    const float* kbase = qkv + (size_t)b * Tt * 3072 + 1024 + hh * 64;
    for (int s = warp; s < n; s += 8) {
        const float* kp = kbase + (size_t)s * 3072;
        float v = qs[lane] * kp[lane] + qs[lane + 32] * kp[lane + 32];
        #pragma unroll
        for (int o = 16; o; o >>= 1) v += __shfl_xor_sync(0xffffffffu, v, o);
        if (lane == 0) scs[s] = v * 0.125f;   // 1/sqrt(64)
    }
    __syncthreads();

    // max
    float m = -3.4e38f;
    for (int s = tid; s < n; s += 256) m = fmaxf(m, scs[s]);
    #pragma unroll
    for (int o = 16; o; o >>= 1) m = fmaxf(m, __shfl_xor_sync(0xffffffffu, m, o));
    if (lane == 0) rmax[warp] = m;
    __syncthreads();
    if (tid == 0) {
        float mm = rmax[0];
        #pragma unroll
        for (int i = 1; i < 8; i++) mm = fmaxf(mm, rmax[i]);
        rmax[0] = mm;
    }
    __syncthreads();
    m = rmax[0];

    // exp + sum
    float ls = 0.f;
    for (int s = tid; s < n; s += 256) {
        float e = expf(scs[s] - m);
        scs[s] = e;
        ls += e;
    }
    #pragma unroll
    for (int o = 16; o; o >>= 1) ls += __shfl_xor_sync(0xffffffffu, ls, o);
    if (lane == 0) rsum[warp] = ls;
    __syncthreads();
    if (tid == 0) {
        float ss = 0.f;
        #pragma unroll
        for (int i = 0; i < 8; i++) ss += rsum[i];
        rsum[0] = ss;
    }
    __syncthreads();
    const float inv = 1.0f / rsum[0];

    // o = w @ V : 64 d-lanes x 4 s-groups
    const int d = tid & 63, g = tid >> 6;
    const float* vb = qkv + (size_t)b * Tt * 3072 + 2048 + hh * 64 + d;
    float acc = 0.f;
    for (int s = g; s < n; s += 4) acc += scs[s] * vb[(size_t)s * 3072];
    osum[g][d] = acc;
    __syncthreads();
    if (g == 0)
        out[(size_t)row * Cc + hh * 64 + d] =
            (osum[0][d] + osum[1][d] + osum[2][d] + osum[3][d]) * inv;
}

// ---------------------------------------------------------------------------
// Host launcher
// ---------------------------------------------------------------------------
extern "C" void kernel_launch(void* const* d_in, const int* in_sizes, int n_in,
                              void* d_out, int out_size)
{
    const int*   idx   = (const int*)  d_in[0];
    const float* tok   = (const float*)d_in[1];
    const float* pos   = (const float*)d_in[2];
    const float* Wq    = (const float*)d_in[3];
    const float* Wk    = (const float*)d_in[4];
    const float* Wv    = (const float*)d_in[5];
    const float* Wo    = (const float*)d_in[6];
    const float* bo    = (const float*)d_in[7];
    const float* ln1s  = (const float*)d_in[8];
    const float* ln1b  = (const float*)d_in[9];
    const float* ln2s  = (const float*)d_in[10];
    const float* ln2b  = (const float*)d_in[11];
    const float* W1    = (const float*)d_in[12];
    const float* b1    = (const float*)d_in[13];
    const float* W2    = (const float*)d_in[14];
    const float* b2    = (const float*)d_in[15];
    const float* lnfs  = (const float*)d_in[16];
    const float* lnfb  = (const float*)d_in[17];
    const float* Wlm   = (const float*)d_in[18];
    const float* blm   = (const float*)d_in[19];
    float* out = (float*)d_out;

    float *px, *ph, *pqkv, *pmlp, *pw;
    cudaGetSymbolAddress((void**)&px,   g_x);
    cudaGetSymbolAddress((void**)&ph,   g_h);
    cudaGetSymbolAddress((void**)&pqkv, g_qkv);
    cudaGetSymbolAddress((void**)&pmlp, g_mlp);
    cudaGetSymbolAddress((void**)&pw,   g_wqkv);

    repack_k<<<4096, 256>>>(Wq, Wk, Wv);
    embed_k<<<(MR * Cc) / 256, 256>>>(idx, tok, pos);

    for (int l = 0; l < Ll; ++l) {
        // ln1
        ln_k<<<MR, 256>>>(px, ln1s + (size_t)l * Cc, ln1b + (size_t)l * Cc, ph);
        // qkv = h @ Wqkv[l]   (2048 x 3072 x 1024)
        gemm_k<false, false, false><<<dim3(3 * Cc / 128, MR / 128), 256>>>(
            ph, pw + (size_t)l * Cc * 3 * Cc, nullptr, nullptr, pqkv, MR, 3 * Cc, Cc);
        // attention -> ph
        attn_k<<<dim3(Tt, Bq * Hh), 256>>>(pqkv, ph);
        // x = x + attn @ Wo[l] + bo[l]
        gemm_k<true, false, true><<<dim3(Cc / 128, MR / 128), 256>>>(
            ph, Wo + (size_t)l * Cc * Cc, bo + (size_t)l * Cc, px, px, MR, Cc, Cc);
        // ln2
        ln_k<<<MR, 256>>>(px, ln2s + (size_t)l * Cc, ln2b + (size_t)l * Cc, ph);
        // mlp hidden = relu(h @ W1 + b1)  (2048 x 4096 x 1024)
        gemm_k<true, true, false><<<dim3(FF / 128, MR / 128), 256>>>(
            ph, W1 + (size_t)l * Cc * FF, b1 + (size_t)l * FF, nullptr, pmlp, MR, FF, Cc);
        // x = x + hidden @ W2 + b2  (2048 x 1024 x 4096)
        gemm_k<true, false, true><<<dim3(Cc / 128, MR / 128), 256>>>(
            pmlp, W2 + (size_t)l * FF * Cc, b2 + (size_t)l * Cc, px, px, MR, Cc, FF);
    }

    // final LN + LM head  (2048 x 32000 x 1024)
    ln_k<<<MR, 256>>>(px, lnfs, lnfb, ph);
    gemm_k<true, false, false><<<dim3(Vv / 128, MR / 128), 256>>>(
        ph, Wlm, blm, nullptr, out, MR, Vv, Cc);
}